// round 10
// baseline (speedup 1.0000x reference)
#include <cuda_runtime.h>
#include <math.h>
#include <stdint.h>

#define N_NODES 4096
#define F_IN    256
#define C_TOT   256
#define HEADS   4
#define F_OUT   64
#define JSPLIT  4
#define NWORDS  (N_NODES / 32)
#define JTILE   64
#define JPER    (N_NODES / JSPLIT)
#define BROW    288   // bytes per jp-row in smem B tile (18 x 16B)

__device__ float    g_h [N_NODES * C_TOT];
__device__ float    g_P1[N_NODES * HEADS];
__device__ float    g_P2[N_NODES * HEADS];
__device__ float    g_Q1[N_NODES * HEADS];
__device__ float    g_Q2[N_NODES * HEADS];
__device__ unsigned g_adjm[N_NODES * NWORDS];
__device__ float    g_part[JSPLIT * HEADS * N_NODES * F_OUT];
__device__ float    g_pden[JSPLIT * HEADS * N_NODES];

// ---------------------------------------------------------------------------
// K1: h = x @ W  + fused attention-logit/exp epilogue.
//  Each CTA: 32 rows x 64 cols, and cols n0..n0+63 are exactly head bx's
//  features -> compute e_i, e_j dots in-register, 16-lane shfl reduce, expf.
// ---------------------------------------------------------------------------
__global__ __launch_bounds__(256) void k_gemm(const float* __restrict__ x,
                                              const float* __restrict__ W,
                                              const float* __restrict__ aa) {
    __shared__ __align__(16) float As[32][20];   // stride 80B = 5x16B (aligned)
    __shared__ __align__(16) float Bs[16][64];
    const int t  = threadIdx.x;
    const int n0 = blockIdx.x * 64;              // = head * 64
    const int m0 = blockIdx.y * 32;
    const int tx = t & 15, ty = t >> 4;

    float acc[2][4];
#pragma unroll
    for (int i = 0; i < 2; ++i)
#pragma unroll
        for (int j = 0; j < 4; ++j) acc[i][j] = 0.f;

    for (int k0 = 0; k0 < F_IN; k0 += 16) {
        if (t < 128) {
            int row = t >> 2, k4 = (t & 3) * 4;
            *(float4*)&As[row][k4] = *(const float4*)&x[(m0 + row) * F_IN + k0 + k4];
        }
        {
            int krow = t >> 4, n4 = (t & 15) * 4;
            *(float4*)&Bs[krow][n4] = *(const float4*)&W[(k0 + krow) * C_TOT + n0 + n4];
        }
        __syncthreads();
#pragma unroll
        for (int kk = 0; kk < 16; ++kk) {
            float a0 = As[ty * 2][kk];
            float a1 = As[ty * 2 + 1][kk];
            float4 b = *(const float4*)&Bs[kk][tx * 4];
            acc[0][0] += a0 * b.x; acc[0][1] += a0 * b.y;
            acc[0][2] += a0 * b.z; acc[0][3] += a0 * b.w;
            acc[1][0] += a1 * b.x; acc[1][1] += a1 * b.y;
            acc[1][2] += a1 * b.z; acc[1][3] += a1 * b.w;
        }
        __syncthreads();
    }
#pragma unroll
    for (int r = 0; r < 2; ++r) {
        float4 v = make_float4(acc[r][0], acc[r][1], acc[r][2], acc[r][3]);
        *(float4*)&g_h[(size_t)(m0 + ty * 2 + r) * C_TOT + n0 + tx * 4] = v;
    }

    // fused exp-table epilogue
    const int f0 = tx * 4;
    float4 a1v = *(const float4*)&aa[f0];
    float4 a2v = *(const float4*)&aa[64 + f0];
#pragma unroll
    for (int r = 0; r < 2; ++r) {
        float ei = acc[r][0] * a1v.x + acc[r][1] * a1v.y
                 + acc[r][2] * a1v.z + acc[r][3] * a1v.w;
        float ej = acc[r][0] * a2v.x + acc[r][1] * a2v.y
                 + acc[r][2] * a2v.z + acc[r][3] * a2v.w;
#pragma unroll
        for (int off = 8; off; off >>= 1) {
            ei += __shfl_down_sync(0xffffffffu, ei, off, 16);
            ej += __shfl_down_sync(0xffffffffu, ej, off, 16);
        }
        if (tx == 0) {
            int idx = (m0 + ty * 2 + r) * HEADS + blockIdx.x;
            g_P1[idx] = expf(ei);
            g_P2[idx] = expf(0.2f * ei);
            g_Q1[idx] = expf(ej);
            g_Q2[idx] = expf(0.2f * ej);
        }
    }
}

// ---------------------------------------------------------------------------
// K3a: pack adjacency to bitmask. int4 loads + shfl-OR word assembly.
// ---------------------------------------------------------------------------
__global__ __launch_bounds__(128) void k_pack(const int* __restrict__ adj) {
    const int i    = blockIdx.x;
    const int w    = threadIdx.x >> 5;
    const int lane = threadIdx.x & 31;
    const size_t rb = (size_t)i * N_NODES;
#pragma unroll
    for (int c = w; c < 32; c += 4) {
        int4 v = *(const int4*)&adj[rb + c * 128 + lane * 4];
        unsigned n = (v.x != 0 ? 1u : 0u) | (v.y != 0 ? 2u : 0u)
                   | (v.z != 0 ? 4u : 0u) | (v.w != 0 ? 8u : 0u);
        unsigned word = n << (4 * (lane & 7));
        word |= __shfl_xor_sync(0xffffffffu, word, 1);
        word |= __shfl_xor_sync(0xffffffffu, word, 2);
        word |= __shfl_xor_sync(0xffffffffu, word, 4);
        if ((lane & 7) == 0)
            g_adjm[i * NWORDS + c * 4 + (lane >> 3)] = word;
    }
}

// ---------------------------------------------------------------------------
// K3b: mma.sync bf16 m16n8k16 aggregation, v5.
//  Warp = 16 i-rows. H staged as bf16x2 j-pairs, f-permuted (p = g*8+nt),
//  XOR-swizzled granules (gr ^ (jp&3)) on 288B jp-rows -> conflict-free
//  LDS.128 B fragments. Denominator via extra ones-B MMA (no ALU den, no
//  epilogue shuffles).
// ---------------------------------------------------------------------------
__device__ __forceinline__ void mma_bf16(float c[4],
                                         unsigned a0, unsigned a1,
                                         unsigned a2, unsigned a3,
                                         unsigned b0, unsigned b1) {
    asm volatile(
        "mma.sync.aligned.m16n8k16.row.col.f32.bf16.bf16.f32 "
        "{%0,%1,%2,%3}, {%4,%5,%6,%7}, {%8,%9}, {%0,%1,%2,%3};"
        : "+f"(c[0]), "+f"(c[1]), "+f"(c[2]), "+f"(c[3])
        : "r"(a0), "r"(a1), "r"(a2), "r"(a3), "r"(b0), "r"(b1));
}
__device__ __forceinline__ unsigned pack_bf16(float lo, float hi) {
    unsigned r;
    asm("cvt.rn.bf16x2.f32 %0, %1, %2;" : "=r"(r) : "f"(hi), "f"(lo));
    return r;
}

__global__ __launch_bounds__(256, 2) void k_aggr_v5() {
    __shared__ __align__(16) char   hsB[32 * BROW];   // 9216 B
    __shared__ __align__(16) float2 qs[JTILE];

    const int t    = threadIdx.x;
    const int w    = t >> 5;
    const int lane = t & 31;
    const int g    = lane >> 2;
    const int tg   = lane & 3;
    const int head = blockIdx.y;
    const int js   = blockIdx.z;
    const int r0   = blockIdx.x * 128 + w * 16 + g;
    const int r1   = r0 + 8;

    const float p1a = g_P1[r0 * HEADS + head], p2a = g_P2[r0 * HEADS + head];
    const float p1b = g_P1[r1 * HEADS + head], p2b = g_P2[r1 * HEADS + head];

    float acc[8][4];
#pragma unroll
    for (int nt = 0; nt < 8; ++nt)
#pragma unroll
        for (int k = 0; k < 4; ++k) acc[nt][k] = 0.f;
    float dacc[4] = {0.f, 0.f, 0.f, 0.f};

    const unsigned ONES = 0x3F803F80u;   // bf16x2 (1.0, 1.0)
    const unsigned* am0 = g_adjm + r0 * NWORDS;
    const unsigned* am1 = g_adjm + r1 * NWORDS;
    const float4*   qs4 = (const float4*)qs;

    for (int tile = 0; tile < JPER / JTILE; ++tile) {
        const int j0 = js * JPER + tile * JTILE;

        __syncthreads();
        // ---- stage H tile: 512 granules; element(jp,p) = bf16x2(h[2jp],h[2jp+1]) at
        //      feature f = nt*8+g, p = g*8+nt; granule gr stored at gr^(jp&3) ----
#pragma unroll
        for (int s = 0; s < 2; ++s) {
            int idx = t + s * 256;
            int jp = idx >> 4, gr = idx & 15;
            int fb = ((gr & 1) << 5) + (gr >> 1);   // f for c=0; +8 per c
            const float* rp0 = &g_h[(size_t)(j0 + 2 * jp) * C_TOT + head * F_OUT + fb];
            const float* rp1 = rp0 + C_TOT;
            uint4 o;
            o.x = pack_bf16(rp0[0],  rp1[0]);
            o.y = pack_bf16(rp0[8],  rp1[8]);
            o.z = pack_bf16(rp0[16], rp1[16]);
            o.w = pack_bf16(rp0[24], rp1[24]);
            *(uint4*)(hsB + jp * BROW + ((gr ^ (jp & 3)) << 4)) = o;
        }
        if (t < JTILE)
            qs[t] = make_float2(g_Q1[(j0 + t) * HEADS + head],
                                g_Q2[(j0 + t) * HEADS + head]);
        __syncthreads();

        const int wd = j0 >> 5;
        const unsigned m0a = am0[wd], m0b = am0[wd + 1];
        const unsigned m1a = am1[wd], m1b = am1[wd + 1];

#pragma unroll
        for (int kk = 0; kk < 4; ++kk) {           // k16 window: j = j0+kk*16 ..+15
            // q pairs: (Q1 je, Q2 je, Q1 jo, Q2 jo)
            float4 qlo = qs4[kk * 8 + tg];
            float4 qhi = qs4[kk * 8 + 4 + tg];

            const unsigned wr0 = (kk < 2) ? m0a : m0b;
            const unsigned wr1 = (kk < 2) ? m1a : m1b;
            const int sh = ((kk & 1) << 4) + 2 * tg;
            const unsigned b0s = wr0 >> sh;
            const unsigned b1s = wr1 >> sh;

            float w00 = (b0s & 1u)   ? fmaxf(p1a * qlo.x, p2a * qlo.y) : 0.f;
            float w01 = (b0s & 2u)   ? fmaxf(p1a * qlo.z, p2a * qlo.w) : 0.f;
            float w10 = (b1s & 1u)   ? fmaxf(p1b * qlo.x, p2b * qlo.y) : 0.f;
            float w11 = (b1s & 2u)   ? fmaxf(p1b * qlo.z, p2b * qlo.w) : 0.f;
            float v00 = (b0s & 256u) ? fmaxf(p1a * qhi.x, p2a * qhi.y) : 0.f;
            float v01 = (b0s & 512u) ? fmaxf(p1a * qhi.z, p2a * qhi.w) : 0.f;
            float v10 = (b1s & 256u) ? fmaxf(p1b * qhi.x, p2b * qhi.y) : 0.f;
            float v11 = (b1s & 512u) ? fmaxf(p1b * qhi.z, p2b * qhi.w) : 0.f;

            unsigned a0 = pack_bf16(w00, w01);   // row r0, k = 2tg,2tg+1
            unsigned a1 = pack_bf16(w10, w11);   // row r1, klo
            unsigned a2 = pack_bf16(v00, v01);   // row r0, k = 8+2tg..
            unsigned a3 = pack_bf16(v10, v11);   // row r1, khi

            // B fragments: 4x conflict-free LDS.128
            const char* rl = hsB + (kk * 8 + tg) * BROW;       // jp_lo row
            const char* rh = rl + 4 * BROW;                    // jp_hi row
            uint4 Blo0 = *(const uint4*)(rl + ((( 2 * g)      ^ tg) << 4));
            uint4 Blo1 = *(const uint4*)(rl + (((2 * g + 1)   ^ tg) << 4));
            uint4 Bhi0 = *(const uint4*)(rh + ((( 2 * g)      ^ tg) << 4));
            uint4 Bhi1 = *(const uint4*)(rh + (((2 * g + 1)   ^ tg) << 4));

            // denominator: B = ones (row sums, replicated across cols)
            mma_bf16(dacc, a0, a1, a2, a3, ONES, ONES);

            mma_bf16(acc[0], a0, a1, a2, a3, Blo0.x, Bhi0.x);
            mma_bf16(acc[1], a0, a1, a2, a3, Blo0.y, Bhi0.y);
            mma_bf16(acc[2], a0, a1, a2, a3, Blo0.z, Bhi0.z);
            mma_bf16(acc[3], a0, a1, a2, a3, Blo0.w, Bhi0.w);
            mma_bf16(acc[4], a0, a1, a2, a3, Blo1.x, Bhi1.x);
            mma_bf16(acc[5], a0, a1, a2, a3, Blo1.y, Bhi1.y);
            mma_bf16(acc[6], a0, a1, a2, a3, Blo1.z, Bhi1.z);
            mma_bf16(acc[7], a0, a1, a2, a3, Blo1.w, Bhi1.w);
        }
    }

    // ---- epilogue: dacc[0]=den(r0), dacc[2]=den(r1), replicated over tg ----
    const size_t pb = (size_t)(js * HEADS + head) * N_NODES;
    if (tg == 0) {
        g_pden[pb + r0] = dacc[0];
        g_pden[pb + r1] = dacc[2];
    }
    float* p0 = &g_part[(pb + r0) * F_OUT];
    float* p1 = &g_part[(pb + r1) * F_OUT];
#pragma unroll
    for (int nt = 0; nt < 8; ++nt) {
        const int f = nt * 8 + tg * 2;
        *(float2*)&p0[f] = make_float2(acc[nt][0], acc[nt][1]);
        *(float2*)&p1[f] = make_float2(acc[nt][2], acc[nt][3]);
    }
}

// ---------------------------------------------------------------------------
// K4: combine partials over j-splits and heads
// ---------------------------------------------------------------------------
__global__ __launch_bounds__(256) void k_combine(float* __restrict__ out) {
    const int t = blockIdx.x * 256 + threadIdx.x;
    const int i = t >> 6;
    const int f = t & 63;
    float v = 0.f;
#pragma unroll
    for (int h = 0; h < HEADS; ++h) {
        float num = 0.f, den = 0.f;
#pragma unroll
        for (int s = 0; s < JSPLIT; ++s) {
            num += g_part[((size_t)(s * HEADS + h) * N_NODES + i) * F_OUT + f];
            den += g_pden[(size_t)(s * HEADS + h) * N_NODES + i];
        }
        v += num / den;
    }
    out[t] = 0.25f * v;
}

// ---------------------------------------------------------------------------
extern "C" void kernel_launch(void* const* d_in, const int* in_sizes, int n_in,
                              void* d_out, int out_size) {
    const float* x   = (const float*)d_in[0];
    const int*   adj = (const int*)  d_in[1];
    const float* W   = (const float*)d_in[2];
    const float* a   = (const float*)d_in[3];
    float* out = (float*)d_out;

    k_gemm<<<dim3(C_TOT / 64, N_NODES / 32), 256>>>(x, W, a);
    k_pack<<<N_NODES, 128>>>(adj);
    k_aggr_v5<<<dim3(N_NODES / 128, HEADS, JSPLIT), 256>>>();
    k_combine<<<(N_NODES * F_OUT) / 256, 256>>>(out);
}

// round 12
// speedup vs baseline: 1.5336x; 1.5336x over previous
#include <cuda_runtime.h>
#include <math.h>
#include <stdint.h>

#define N_NODES 4096
#define F_IN    256
#define C_TOT   256
#define HEADS   4
#define F_OUT   64
#define JSPLIT  4
#define NWORDS  (N_NODES / 32)
#define JTILE   64
#define JPER    (N_NODES / JSPLIT)
#define NT      (JPER / JTILE)     // 16 tiles per CTA
#define HSTR    72

__device__ float    g_h [N_NODES * C_TOT];
__device__ float2   g_Pq[HEADS * N_NODES];   // (exp(e_i), exp(0.2 e_i)) per [head][n]
__device__ float2   g_Qq[HEADS * N_NODES];   // (exp(e_j), exp(0.2 e_j)) per [head][n]
__device__ unsigned g_adjm[N_NODES * NWORDS];
__device__ float    g_part[JSPLIT * HEADS * N_NODES * F_OUT];
__device__ float    g_pden[JSPLIT * HEADS * N_NODES];

// ---------------- cp.async helpers ----------------
__device__ __forceinline__ void cp16(uint32_t dst, const void* src) {
    asm volatile("cp.async.cg.shared.global [%0], [%1], 16;" :: "r"(dst), "l"(src));
}
#define CP_COMMIT() asm volatile("cp.async.commit_group;" ::: "memory")
#define CP_WAIT1()  asm volatile("cp.async.wait_group 1;" ::: "memory")
#define CP_WAIT0()  asm volatile("cp.async.wait_group 0;" ::: "memory")

// ---------------------------------------------------------------------------
// K1: h = x @ W  (proven 64x64 tiling) + fused exp-table epilogue.
//  CTA covers cols n0 = head*64 -> per-thread partial dots + 16-lane reduce.
// ---------------------------------------------------------------------------
__global__ __launch_bounds__(256) void k_gemm(const float* __restrict__ x,
                                              const float* __restrict__ W,
                                              const float* __restrict__ aa) {
    __shared__ __align__(16) float As[16][64];   // [k][m]
    __shared__ __align__(16) float Bs[16][64];   // [k][n]
    const int t  = threadIdx.x;
    const int n0 = blockIdx.x * 64;              // head = blockIdx.x
    const int m0 = blockIdx.y * 64;
    const int tx = t & 15, ty = t >> 4;

    float acc[4][4];
#pragma unroll
    for (int i = 0; i < 4; ++i)
#pragma unroll
        for (int j = 0; j < 4; ++j) acc[i][j] = 0.f;

    for (int k0 = 0; k0 < F_IN; k0 += 16) {
        {
            int row = t >> 2, k4 = (t & 3) * 4;
            float4 v = *(const float4*)&x[(m0 + row) * F_IN + k0 + k4];
            As[k4 + 0][row] = v.x; As[k4 + 1][row] = v.y;
            As[k4 + 2][row] = v.z; As[k4 + 3][row] = v.w;
        }
        {
            int krow = t >> 4, n4 = (t & 15) * 4;
            *(float4*)&Bs[krow][n4] = *(const float4*)&W[(k0 + krow) * C_TOT + n0 + n4];
        }
        __syncthreads();
#pragma unroll
        for (int kk = 0; kk < 16; ++kk) {
            float a[4], b[4];
            *(float4*)a = *(float4*)&As[kk][ty * 4];
            *(float4*)b = *(float4*)&Bs[kk][tx * 4];
#pragma unroll
            for (int i = 0; i < 4; ++i)
#pragma unroll
                for (int j = 0; j < 4; ++j) acc[i][j] += a[i] * b[j];
        }
        __syncthreads();
    }
#pragma unroll
    for (int i = 0; i < 4; ++i) {
        float4 v = make_float4(acc[i][0], acc[i][1], acc[i][2], acc[i][3]);
        *(float4*)&g_h[(size_t)(m0 + ty * 4 + i) * C_TOT + n0 + tx * 4] = v;
    }

    // fused exp-table epilogue: reduce over this CTA's 64 head-features
    const int f0 = tx * 4;
    float4 a1v = *(const float4*)&aa[f0];
    float4 a2v = *(const float4*)&aa[64 + f0];
#pragma unroll
    for (int i = 0; i < 4; ++i) {
        float ei = acc[i][0] * a1v.x + acc[i][1] * a1v.y
                 + acc[i][2] * a1v.z + acc[i][3] * a1v.w;
        float ej = acc[i][0] * a2v.x + acc[i][1] * a2v.y
                 + acc[i][2] * a2v.z + acc[i][3] * a2v.w;
#pragma unroll
        for (int off = 8; off; off >>= 1) {
            ei += __shfl_down_sync(0xffffffffu, ei, off, 16);
            ej += __shfl_down_sync(0xffffffffu, ej, off, 16);
        }
        if (tx == 0) {
            int idx = blockIdx.x * N_NODES + m0 + ty * 4 + i;
            g_Pq[idx] = make_float2(expf(ei), expf(0.2f * ei));
            g_Qq[idx] = make_float2(expf(ej), expf(0.2f * ej));
        }
    }
}

// ---------------------------------------------------------------------------
// K3a: pack adjacency to bitmask. int4 loads + shfl-OR word assembly.
// ---------------------------------------------------------------------------
__global__ __launch_bounds__(128) void k_pack(const int* __restrict__ adj) {
    const int i    = blockIdx.x;
    const int w    = threadIdx.x >> 5;
    const int lane = threadIdx.x & 31;
    const size_t rb = (size_t)i * N_NODES;
#pragma unroll
    for (int c = w; c < 32; c += 4) {
        int4 v = *(const int4*)&adj[rb + c * 128 + lane * 4];
        unsigned n = (v.x != 0 ? 1u : 0u) | (v.y != 0 ? 2u : 0u)
                   | (v.z != 0 ? 4u : 0u) | (v.w != 0 ? 8u : 0u);
        unsigned word = n << (4 * (lane & 7));
        word |= __shfl_xor_sync(0xffffffffu, word, 1);
        word |= __shfl_xor_sync(0xffffffffu, word, 2);
        word |= __shfl_xor_sync(0xffffffffu, word, 4);
        if ((lane & 7) == 0)
            g_adjm[i * NWORDS + c * 4 + (lane >> 3)] = word;
    }
}

// ---------------------------------------------------------------------------
// K3b: tf32 mma.sync aggregation, v6 = R2 structure (proven fastest inner
//  loop) + cp.async double-buffered staging + JSPLIT=4.
//  Warp = 16 i-rows, CTA = 64 i-rows x 1 head x 1 j-quarter.
//  H staged RAW fp32 (HMMA.TF32 truncates mantissa in HW) -> staging is a
//  pure async copy fully overlapped with compute.
// ---------------------------------------------------------------------------
__device__ __forceinline__ void mma_tf32(float c[4],
                                         unsigned a0, unsigned a1,
                                         unsigned a2, unsigned a3,
                                         unsigned b0, unsigned b1) {
    asm volatile(
        "mma.sync.aligned.m16n8k8.row.col.f32.tf32.tf32.f32 "
        "{%0,%1,%2,%3}, {%4,%5,%6,%7}, {%8,%9}, {%0,%1,%2,%3};"
        : "+f"(c[0]), "+f"(c[1]), "+f"(c[2]), "+f"(c[3])
        : "r"(a0), "r"(a1), "r"(a2), "r"(a3), "r"(b0), "r"(b1));
}
__device__ __forceinline__ unsigned to_tf32(float x) {
    unsigned u;
    asm("cvt.rna.tf32.f32 %0, %1;" : "=r"(u) : "f"(x));
    return u;
}

__global__ __launch_bounds__(128) void k_aggr_v6() {
    __shared__ __align__(16) float  hs[2][JTILE * HSTR];   // 2 x 18 KB
    __shared__ __align__(16) float2 qs[2][JTILE];          // 2 x 512 B

    const int t    = threadIdx.x;
    const int w    = t >> 5;
    const int lane = t & 31;
    const int g    = lane >> 2;
    const int tg   = lane & 3;
    const int head = blockIdx.y;
    const int js   = blockIdx.z;
    const int i0   = blockIdx.x * 64;
    const int row0 = i0 + w * 16 + g;
    const int row1 = row0 + 8;

    const float2 pa = g_Pq[head * N_NODES + row0];
    const float2 pb = g_Pq[head * N_NODES + row1];

    float acc[8][4];
#pragma unroll
    for (int nt = 0; nt < 8; ++nt)
#pragma unroll
        for (int k = 0; k < 4; ++k) acc[nt][k] = 0.f;
    float d0 = 0.f, d1 = 0.f;

    const unsigned* am0 = g_adjm + row0 * NWORDS;
    const unsigned* am1 = g_adjm + row1 * NWORDS;

    const uint32_t hs0 = (uint32_t)__cvta_generic_to_shared(&hs[0][0]);
    const uint32_t hs1 = (uint32_t)__cvta_generic_to_shared(&hs[1][0]);
    const uint32_t qs0 = (uint32_t)__cvta_generic_to_shared(&qs[0][0]);
    const uint32_t qs1 = (uint32_t)__cvta_generic_to_shared(&qs[1][0]);
    const int jbase = js * JPER;

    // ---- stage tile 0 into buffer 0 ----
    {
        const int j0 = jbase;
#pragma unroll
        for (int s = 0; s < 8; ++s) {
            int c = t + s * 128;
            int jj = c >> 4, cc = c & 15;
            cp16(hs0 + (jj * HSTR + cc * 4) * 4,
                 &g_h[(size_t)(j0 + jj) * C_TOT + head * F_OUT + cc * 4]);
        }
        if (t < 32)
            cp16(qs0 + t * 16, &g_Qq[head * N_NODES + j0 + t * 2]);
    }
    CP_COMMIT();

    for (int tile = 0; tile < NT; ++tile) {
        const int buf = tile & 1;
        const int j0  = jbase + tile * JTILE;

        // ---- stage tile+1 into other buffer (fully async) ----
        if (tile + 1 < NT) {
            const int jn = j0 + JTILE;
            const uint32_t hb = buf ? hs0 : hs1;
            const uint32_t qb = buf ? qs0 : qs1;
#pragma unroll
            for (int s = 0; s < 8; ++s) {
                int c = t + s * 128;
                int jj = c >> 4, cc = c & 15;
                cp16(hb + (jj * HSTR + cc * 4) * 4,
                     &g_h[(size_t)(jn + jj) * C_TOT + head * F_OUT + cc * 4]);
            }
            if (t < 32)
                cp16(qb + t * 16, &g_Qq[head * N_NODES + jn + t * 2]);
            CP_COMMIT();
            CP_WAIT1();
        } else {
            CP_WAIT0();
        }
        __syncthreads();

        const float  (*hsb)[JTILE * HSTR] = &hs[buf];
        const float2* qsb = qs[buf];
        const int wd = j0 >> 5;
        const unsigned m0a = am0[wd], m0b = am0[wd + 1];
        const unsigned m1a = am1[wd], m1b = am1[wd + 1];

#pragma unroll
        for (int kk = 0; kk < 8; ++kk) {
            const unsigned w0 = (kk < 4) ? m0a : m0b;
            const unsigned w1 = (kk < 4) ? m1a : m1b;
            const int sl   = (kk * 8) & 31;
            const int j_lo = kk * 8 + tg;
            const int j_hi = j_lo + 4;
            const float2 qlo = qsb[j_lo];
            const float2 qhi = qsb[j_hi];

            float v00 = fmaxf(pa.x * qlo.x, pa.y * qlo.y);
            float v10 = fmaxf(pb.x * qlo.x, pb.y * qlo.y);
            float v01 = fmaxf(pa.x * qhi.x, pa.y * qhi.y);
            float v11 = fmaxf(pb.x * qhi.x, pb.y * qhi.y);
            float a00 = ((w0 >> (sl + tg))     & 1u) ? v00 : 0.f;
            float a10 = ((w1 >> (sl + tg))     & 1u) ? v10 : 0.f;
            float a01 = ((w0 >> (sl + tg + 4)) & 1u) ? v01 : 0.f;
            float a11 = ((w1 >> (sl + tg + 4)) & 1u) ? v11 : 0.f;

            unsigned ua0 = to_tf32(a00);
            unsigned ua1 = to_tf32(a10);
            unsigned ua2 = to_tf32(a01);
            unsigned ua3 = to_tf32(a11);
            d0 += __uint_as_float(ua0) + __uint_as_float(ua2);
            d1 += __uint_as_float(ua1) + __uint_as_float(ua3);

            const float* blo = &(*hsb)[j_lo * HSTR + g];
            const float* bhi = &(*hsb)[j_hi * HSTR + g];
#pragma unroll
            for (int nt = 0; nt < 8; ++nt) {
                unsigned b0 = __float_as_uint(blo[nt * 8]);
                unsigned b1 = __float_as_uint(bhi[nt * 8]);
                mma_tf32(acc[nt], ua0, ua1, ua2, ua3, b0, b1);
            }
        }
        __syncthreads();   // compute done before next-next stage overwrites buf
    }

    // ---- epilogue: quad-reduce denominators, write partials ----
    d0 += __shfl_xor_sync(0xffffffffu, d0, 1);
    d0 += __shfl_xor_sync(0xffffffffu, d0, 2);
    d1 += __shfl_xor_sync(0xffffffffu, d1, 1);
    d1 += __shfl_xor_sync(0xffffffffu, d1, 2);

    const size_t pb2 = (size_t)(js * HEADS + head) * N_NODES;
    if (tg == 0) {
        g_pden[pb2 + row0] = d0;
        g_pden[pb2 + row1] = d1;
    }
    float* p0 = &g_part[(pb2 + row0) * F_OUT];
    float* p1 = &g_part[(pb2 + row1) * F_OUT];
#pragma unroll
    for (int nt = 0; nt < 8; ++nt) {
        const int f = nt * 8 + tg * 2;
        *(float2*)&p0[f] = make_float2(acc[nt][0], acc[nt][1]);
        *(float2*)&p1[f] = make_float2(acc[nt][2], acc[nt][3]);
    }
}

// ---------------------------------------------------------------------------
// K4: combine partials over j-splits and heads
// ---------------------------------------------------------------------------
__global__ __launch_bounds__(256) void k_combine(float* __restrict__ out) {
    const int t = blockIdx.x * 256 + threadIdx.x;
    const int i = t >> 6;
    const int f = t & 63;
    float v = 0.f;
#pragma unroll
    for (int h = 0; h < HEADS; ++h) {
        float num = 0.f, den = 0.f;
#pragma unroll
        for (int s = 0; s < JSPLIT; ++s) {
            num += g_part[((size_t)(s * HEADS + h) * N_NODES + i) * F_OUT + f];
            den += g_pden[(size_t)(s * HEADS + h) * N_NODES + i];
        }
        v += num / den;
    }
    out[t] = 0.25f * v;
}

// ---------------------------------------------------------------------------
extern "C" void kernel_launch(void* const* d_in, const int* in_sizes, int n_in,
                              void* d_out, int out_size) {
    const float* x   = (const float*)d_in[0];
    const int*   adj = (const int*)  d_in[1];
    const float* W   = (const float*)d_in[2];
    const float* a   = (const float*)d_in[3];
    float* out = (float*)d_out;

    k_gemm<<<dim3(HEADS, N_NODES / 64), 256>>>(x, W, a);
    k_pack<<<N_NODES, 128>>>(adj);
    k_aggr_v6<<<dim3(N_NODES / 64, HEADS, JSPLIT), 128>>>();
    k_combine<<<(N_NODES * F_OUT) / 256, 256>>>(out);
}